// round 6
// baseline (speedup 1.0000x reference)
#include <cuda_runtime.h>
#include <cuda_bf16.h>
#include <cstdint>
#include <math.h>

// ---------------- static scratch (no allocs allowed) ----------------
__device__ __align__(16) __nv_bfloat16 g_A_hi[102760448];   // 8192x12544
__device__ __align__(16) __nv_bfloat16 g_A_lo[102760448];
__device__ __align__(16) __nv_bfloat16 g_w13_hi[25690112];  // [w_fc1;w_fc3] 2048x12544
__device__ __align__(16) __nv_bfloat16 g_w13_lo[25690112];
__device__ __align__(16) __nv_bfloat16 g_w24_hi[2097152];   // [w_fc2;w_fc4] 2048x1024
__device__ __align__(16) __nv_bfloat16 g_w24_lo[2097152];
__device__ __align__(16) __nv_bfloat16 g_act1_hi[16777216]; // 8192x2048
__device__ __align__(16) __nv_bfloat16 g_act1_lo[16777216];
__device__ __align__(16) float         g_act2[16777216];    // 8192x2048
__device__ __align__(16) float         g_heads[524288];     // 8192x64
__device__ float g_bias1[2048];
__device__ float g_bias2[2048];

// ---------------- helpers ----------------
__device__ __forceinline__ uint32_t smem_u32(const void* p) {
    uint32_t a;
    asm("{ .reg .u64 t; cvta.to.shared.u64 t, %1; cvt.u32.u64 %0, t; }" : "=r"(a) : "l"(p));
    return a;
}
__device__ __forceinline__ uint32_t swz(uint32_t x) { return x ^ ((x >> 3) & 0x70); }

__device__ __forceinline__ void cp16(uint32_t dst, const void* src) {
    asm volatile("cp.async.cg.shared.global [%0], [%1], 16;"
                 :: "r"(dst), "l"(__cvta_generic_to_global(src)) : "memory");
}
#define CP_COMMIT() asm volatile("cp.async.commit_group;" ::: "memory")
#define CP_WAIT2()  asm volatile("cp.async.wait_group 2;" ::: "memory")

__device__ __forceinline__ void ldsm4(uint32_t* r, uint32_t a) {
    asm volatile("ldmatrix.sync.aligned.m8n8.x4.shared.b16 {%0,%1,%2,%3}, [%4];"
                 : "=r"(r[0]), "=r"(r[1]), "=r"(r[2]), "=r"(r[3]) : "r"(a));
}
__device__ __forceinline__ void mma16816(float* d, const uint32_t* a, uint32_t b0, uint32_t b1) {
    asm volatile(
        "mma.sync.aligned.m16n8k16.row.col.f32.bf16.bf16.f32 "
        "{%0,%1,%2,%3}, {%4,%5,%6,%7}, {%8,%9}, {%0,%1,%2,%3};"
        : "+f"(d[0]), "+f"(d[1]), "+f"(d[2]), "+f"(d[3])
        : "r"(a[0]), "r"(a[1]), "r"(a[2]), "r"(a[3]), "r"(b0), "r"(b1));
}
__device__ __forceinline__ uint32_t bf2u(__nv_bfloat16 a, __nv_bfloat16 b) {
    __nv_bfloat162 t; t.x = a; t.y = b;
    return *reinterpret_cast<uint32_t*>(&t);
}

// stage: A_hi 16K | A_lo 16K | B_hi 16K | B_lo 16K = 64KB, 3 stages
static constexpr int STG = 65536;
static constexpr int SMEM_BYTES = 3 * STG;

// ============ GEMM: C[128x128] = split-bf16 A @ B^T, 3 mma passes ============
// MODE 0: bias+relu -> split bf16 store to g_act1 (GEMM1)
// MODE 1: bias+relu -> fp32 store to g_act2 (GEMM2)
template <int MODE>
__global__ void __launch_bounds__(256, 1) gemm_kernel(
    const __nv_bfloat16* __restrict__ Ah, const __nv_bfloat16* __restrict__ Al,
    const __nv_bfloat16* __restrict__ Bh, const __nv_bfloat16* __restrict__ Bl,
    const float* __restrict__ bias, int K, int ldA, int a_split)
{
    extern __shared__ char smem[];
    const uint32_t sbase = smem_u32(smem);
    const int tid = threadIdx.x, wid = tid >> 5, lid = tid & 31;
    const int n_base = blockIdx.x * 128;
    const int m_base = blockIdx.y * 128;
    const int a_off = (a_split && n_base >= 1024) ? 1024 : 0;
    const int NS = K >> 6;

    const int wm = wid & 3, wn = wid >> 2;       // warp tile 32x64
    const int m0 = wm * 32, n0 = wn * 64;
    const int lrow = (lid & 7) | (((lid >> 3) & 1) << 3);  // 0..15
    const int lcol = (lid >> 4) * 16;                      // 0 or 16 bytes

    // cp.async thread mapping: 4 iters, idx -> row (0..127), chunk c (0..7)
    const int ld_row0 = tid >> 3, ld_c = tid & 7;

    float acc[2][8][4];
#pragma unroll
    for (int mt = 0; mt < 2; ++mt)
#pragma unroll
        for (int j = 0; j < 8; ++j)
#pragma unroll
            for (int q = 0; q < 4; ++q) acc[mt][j][q] = 0.f;

    auto load_stage = [&](int s) {
        if (s < NS) {
            const size_t kb = (size_t)s * 64;
            const uint32_t so = sbase + (uint32_t)(s % 3) * STG;
#pragma unroll
            for (int i = 0; i < 4; ++i) {
                const int row = ld_row0 + i * 32;
                const uint32_t sw = swz((uint32_t)(row * 128 + ld_c * 16));
                const size_t ga = (size_t)(m_base + row) * ldA + a_off + kb + ld_c * 8;
                const size_t gb = (size_t)(n_base + row) * K + kb + ld_c * 8;
                cp16(so + sw,         Ah + ga);
                cp16(so + 16384 + sw, Al + ga);
                cp16(so + 32768 + sw, Bh + gb);
                cp16(so + 49152 + sw, Bl + gb);
            }
        }
        CP_COMMIT();
    };

    load_stage(0);
    load_stage(1);

#pragma unroll 1
    for (int s = 0; s < NS; ++s) {
        load_stage(s + 2);
        CP_WAIT2();
        __syncthreads();
        const uint32_t so = sbase + (uint32_t)(s % 3) * STG;
#pragma unroll
        for (int kk = 0; kk < 4; ++kk) {
            const int kb2 = kk * 32;
            uint32_t ah[2][4], al[2][4], bh[4][4], bl[4][4];
#pragma unroll
            for (int mt = 0; mt < 2; ++mt) {
                const uint32_t off = swz((uint32_t)((m0 + mt * 16 + lrow) * 128 + kb2 + lcol));
                ldsm4(ah[mt], so + off);
                ldsm4(al[mt], so + 16384 + off);
            }
#pragma unroll
            for (int j2 = 0; j2 < 4; ++j2) {
                const uint32_t off = swz((uint32_t)((n0 + j2 * 16 + lrow) * 128 + kb2 + lcol));
                ldsm4(bh[j2], so + 32768 + off);
                ldsm4(bl[j2], so + 49152 + off);
            }
#pragma unroll
            for (int mt = 0; mt < 2; ++mt)
#pragma unroll
                for (int j2 = 0; j2 < 4; ++j2)
#pragma unroll
                    for (int h = 0; h < 2; ++h) {
                        float* d = acc[mt][j2 * 2 + h];
                        mma16816(d, ah[mt], bh[j2][h], bh[j2][2 + h]);
                        mma16816(d, ah[mt], bl[j2][h], bl[j2][2 + h]);
                        mma16816(d, al[mt], bh[j2][h], bh[j2][2 + h]);
                    }
        }
        __syncthreads();
    }

    // epilogue
    const int grp = lid >> 2, qd = lid & 3;
#pragma unroll
    for (int mt = 0; mt < 2; ++mt)
#pragma unroll
        for (int j = 0; j < 8; ++j)
#pragma unroll
            for (int h = 0; h < 2; ++h) {   // h=0: rows grp, h=1: rows grp+8
                const int row = m_base + m0 + mt * 16 + grp + h * 8;
                const int col = n_base + n0 + j * 8 + qd * 2;
                const float b0 = __ldg(bias + col), b1 = __ldg(bias + col + 1);
                float v0 = fmaxf(acc[mt][j][2 * h]     + b0, 0.f);
                float v1 = fmaxf(acc[mt][j][2 * h + 1] + b1, 0.f);
                const size_t o = (size_t)row * 2048 + col;
                if (MODE == 0) {
                    __nv_bfloat16 h0 = __float2bfloat16_rn(v0), h1 = __float2bfloat16_rn(v1);
                    *reinterpret_cast<uint32_t*>(g_act1_hi + o) = bf2u(h0, h1);
                    *reinterpret_cast<uint32_t*>(g_act1_lo + o) =
                        bf2u(__float2bfloat16_rn(v0 - __bfloat162float(h0)),
                             __float2bfloat16_rn(v1 - __bfloat162float(h1)));
                } else {
                    float2 f; f.x = v0; f.y = v1;
                    *reinterpret_cast<float2*>(g_act2 + o) = f;
                }
            }
}

// ============ fp32 -> bf16 hi/lo split conversion ============
__global__ void __launch_bounds__(256) conv_split(
    const float* __restrict__ s, __nv_bfloat16* __restrict__ hi,
    __nv_bfloat16* __restrict__ lo, size_t n4)
{
    const size_t i = (size_t)blockIdx.x * 256 + threadIdx.x;
    if (i >= n4) return;
    float4 v = reinterpret_cast<const float4*>(s)[i];
    __nv_bfloat16 h0 = __float2bfloat16_rn(v.x), h1 = __float2bfloat16_rn(v.y);
    __nv_bfloat16 h2 = __float2bfloat16_rn(v.z), h3 = __float2bfloat16_rn(v.w);
    uint2 hp; hp.x = bf2u(h0, h1); hp.y = bf2u(h2, h3);
    reinterpret_cast<uint2*>(hi)[i] = hp;
    uint2 lp;
    lp.x = bf2u(__float2bfloat16_rn(v.x - __bfloat162float(h0)),
                __float2bfloat16_rn(v.y - __bfloat162float(h1)));
    lp.y = bf2u(__float2bfloat16_rn(v.z - __bfloat162float(h2)),
                __float2bfloat16_rn(v.w - __bfloat162float(h3)));
    reinterpret_cast<uint2*>(lo)[i] = lp;
}

__global__ void pack_bias(const float* b1, const float* b3,
                          const float* b2, const float* b4)
{
    int i = threadIdx.x;
    g_bias1[i] = b1[i]; g_bias1[1024 + i] = b3[i];
    g_bias2[i] = b2[i]; g_bias2[1024 + i] = b4[i];
}

// ============ Heads: 53 dot-products of length 1024 per row ============
__global__ void __launch_bounds__(512) heads_kernel(
    const float* __restrict__ w_cls, const float* __restrict__ b_cls,
    const float* __restrict__ w_delta, const float* __restrict__ b_delta,
    const float* __restrict__ w_pos, const float* __restrict__ b_pos,
    const float* __restrict__ w_emb, const float* __restrict__ b_emb)
{
    const int wid = threadIdx.x >> 5, lid = threadIdx.x & 31;
    const int row = blockIdx.x * 16 + wid;
#pragma unroll 1
    for (int o = 0; o < 53; ++o) {
        const float* Wp; const float* bp; int wr, ac;
        if (o < 3)       { Wp = w_cls;   bp = b_cls;   wr = o;      ac = 0; }
        else if (o < 15) { Wp = w_delta; bp = b_delta; wr = o - 3;  ac = 0; }
        else if (o < 21) { Wp = w_pos;   bp = b_pos;   wr = o - 15; ac = 0; }
        else             { Wp = w_emb;   bp = b_emb;   wr = o - 21; ac = 1024; }
        const float* a = g_act2 + (size_t)row * 2048 + ac;
        const float* w = Wp + (size_t)wr * 1024;
        float s = 0.f;
#pragma unroll 8
        for (int k = lid; k < 1024; k += 32) s += a[k] * w[k];
#pragma unroll
        for (int d = 16; d; d >>= 1) s += __shfl_xor_sync(0xFFFFFFFFu, s, d);
        if (lid == 0) g_heads[(size_t)row * 64 + o] = s + bp[wr];
    }
}

// ============ Postprocess: softmax + bbox restore + emb repeat ============
__global__ void __launch_bounds__(128) post_kernel(
    const float* __restrict__ rois, float* __restrict__ out, int out_size)
{
    const int n = blockIdx.x * blockDim.x + threadIdx.x;
    if (n >= 8192) return;
    const float* h = g_heads + (size_t)n * 64;
    float c0 = h[0], c1 = h[1], c2 = h[2];
    float m = fmaxf(c0, fmaxf(c1, c2));
    float e0 = expf(c0 - m), e1 = expf(c1 - m), e2 = expf(c2 - m);
    float inv = 1.f / (e0 + e1 + e2);
    float sc0 = e1 * inv, sc1 = e2 * inv;
    float x1 = rois[n * 5 + 1], y1 = rois[n * 5 + 2];
    float x2 = rois[n * 5 + 3], y2 = rois[n * 5 + 4];
    float bw = x2 - x1, bh = y2 - y1;
    float cx = x1 + 0.5f * bw, cy = y1 + 0.5f * bh;
#pragma unroll
    for (int j = 0; j < 2; ++j) {
        float d0 = h[7 + 4 * j] * 0.1f, d1 = h[8 + 4 * j] * 0.1f;
        float d2 = h[9 + 4 * j] * 0.2f, d3 = h[10 + 4 * j] * 0.2f;
        float p0 = h[17 + 2 * j] * 0.1f, p1 = h[18 + 2 * j] * 0.1f;
        float pcx = d0 * bw + cx, pcy = d1 * bh + cy;
        float pw = expf(d2) * bw, phh = expf(d3) * bh;
        float px = p0 * bw + cx, py = p1 * bh + cy;
        float* ob = out + (size_t)(2 * n + j) * 8;
        ob[0] = pcx - 0.5f * pw;  ob[1] = pcy - 0.5f * phh;
        ob[2] = pcx + 0.5f * pw;  ob[3] = pcy + 0.5f * phh;
        ob[4] = px; ob[5] = py;
        ob[6] = j ? sc1 : sc0;
        ob[7] = (float)(j + 1);
        float* oe = out + 131072 + (size_t)(2 * n + j) * 32;
#pragma unroll
        for (int t = 0; t < 32; ++t) oe[t] = h[21 + t];
    }
    if (n == 0 && out_size > 655360) out[655360] = 2.0f;
}

// ============ launch ============
extern "C" void kernel_launch(void* const* d_in, const int* in_sizes, int n_in,
                              void* d_out, int out_size) {
    const float* pool   = (const float*)d_in[0];
    const float* rois   = (const float*)d_in[1];
    const float* w_fc1  = (const float*)d_in[2];
    const float* b_fc1  = (const float*)d_in[3];
    const float* w_fc2  = (const float*)d_in[4];
    const float* b_fc2  = (const float*)d_in[5];
    const float* w_fc3  = (const float*)d_in[6];
    const float* b_fc3  = (const float*)d_in[7];
    const float* w_fc4  = (const float*)d_in[8];
    const float* b_fc4  = (const float*)d_in[9];
    const float* w_cls  = (const float*)d_in[10];
    const float* b_cls  = (const float*)d_in[11];
    const float* w_delta= (const float*)d_in[12];
    const float* b_delta= (const float*)d_in[13];
    const float* w_pos  = (const float*)d_in[14];
    const float* b_pos  = (const float*)d_in[15];
    const float* w_emb  = (const float*)d_in[16];
    const float* b_emb  = (const float*)d_in[17];
    float* out = (float*)d_out;

    __nv_bfloat16 *Ah, *Al, *W13h, *W13l, *W24h, *W24l, *A1h, *A1l;
    cudaGetSymbolAddress((void**)&Ah,   g_A_hi);
    cudaGetSymbolAddress((void**)&Al,   g_A_lo);
    cudaGetSymbolAddress((void**)&W13h, g_w13_hi);
    cudaGetSymbolAddress((void**)&W13l, g_w13_lo);
    cudaGetSymbolAddress((void**)&W24h, g_w24_hi);
    cudaGetSymbolAddress((void**)&W24l, g_w24_lo);
    cudaGetSymbolAddress((void**)&A1h,  g_act1_hi);
    cudaGetSymbolAddress((void**)&A1l,  g_act1_lo);
    float* bias1; float* bias2;
    cudaGetSymbolAddress((void**)&bias1, g_bias1);
    cudaGetSymbolAddress((void**)&bias2, g_bias2);

    cudaFuncSetAttribute(gemm_kernel<0>, cudaFuncAttributeMaxDynamicSharedMemorySize, SMEM_BYTES);
    cudaFuncSetAttribute(gemm_kernel<1>, cudaFuncAttributeMaxDynamicSharedMemorySize, SMEM_BYTES);

    // conversion pre-pass
    conv_split<<<100352, 256>>>(pool,  Ah,              Al,              25690112);
    conv_split<<<12544,  256>>>(w_fc1, W13h,            W13l,            3211264);
    conv_split<<<12544,  256>>>(w_fc3, W13h + 12845056, W13l + 12845056, 3211264);
    conv_split<<<1024,   256>>>(w_fc2, W24h,            W24l,            262144);
    conv_split<<<1024,   256>>>(w_fc4, W24h + 1048576,  W24l + 1048576,  262144);
    pack_bias<<<1, 1024>>>(b_fc1, b_fc3, b_fc2, b_fc4);

    gemm_kernel<0><<<dim3(16, 64), 256, SMEM_BYTES>>>(Ah, Al, W13h, W13l, bias1, 12544, 12544, 0);
    gemm_kernel<1><<<dim3(16, 64), 256, SMEM_BYTES>>>(A1h, A1l, W24h, W24l, bias2, 1024, 2048, 1);
    heads_kernel<<<512, 512>>>(w_cls, b_cls, w_delta, b_delta, w_pos, b_pos, w_emb, b_emb);
    post_kernel<<<64, 128>>>(rois, out, out_size);
}

// round 9
// speedup vs baseline: 1.3480x; 1.3480x over previous
#include <cuda_runtime.h>
#include <cuda_bf16.h>
#include <cstdint>
#include <math.h>

// ---------------- static scratch (no allocs allowed) ----------------
__device__ __align__(16) __nv_bfloat16 g_A_hi[102760448];   // 8192x12544
__device__ __align__(16) __nv_bfloat16 g_A_lo[102760448];
__device__ __align__(16) __nv_bfloat16 g_w13_hi[25690112];  // [w_fc1;w_fc3] 2048x12544
__device__ __align__(16) __nv_bfloat16 g_w13_lo[25690112];
__device__ __align__(16) __nv_bfloat16 g_w24_hi[2097152];   // [w_fc2;w_fc4] 2048x1024
__device__ __align__(16) __nv_bfloat16 g_w24_lo[2097152];
__device__ __align__(16) __nv_bfloat16 g_act1_hi[16777216]; // 8192x2048
__device__ __align__(16) __nv_bfloat16 g_act1_lo[16777216];
__device__ __align__(16) float         g_act2[16777216];    // 8192x2048
__device__ __align__(16) float         g_heads[524288];     // 8192x64

// ---------------- helpers ----------------
__device__ __forceinline__ uint32_t smem_u32(const void* p) {
    uint32_t a;
    asm("{ .reg .u64 t; cvta.to.shared.u64 t, %1; cvt.u32.u64 %0, t; }" : "=r"(a) : "l"(p));
    return a;
}
__device__ __forceinline__ uint32_t swz(uint32_t x) { return x ^ ((x >> 3) & 0x70); }

__device__ __forceinline__ void cp16(uint32_t dst, const void* src) {
    asm volatile("cp.async.cg.shared.global [%0], [%1], 16;"
                 :: "r"(dst), "l"(__cvta_generic_to_global(src)) : "memory");
}
#define CP_COMMIT() asm volatile("cp.async.commit_group;" ::: "memory")
#define CP_WAIT1()  asm volatile("cp.async.wait_group 1;" ::: "memory")

__device__ __forceinline__ void ldsm4(uint32_t* r, uint32_t a) {
    asm volatile("ldmatrix.sync.aligned.m8n8.x4.shared.b16 {%0,%1,%2,%3}, [%4];"
                 : "=r"(r[0]), "=r"(r[1]), "=r"(r[2]), "=r"(r[3]) : "r"(a));
}
__device__ __forceinline__ void mma16816(float* d, const uint32_t* a, uint32_t b0, uint32_t b1) {
    asm volatile(
        "mma.sync.aligned.m16n8k16.row.col.f32.bf16.bf16.f32 "
        "{%0,%1,%2,%3}, {%4,%5,%6,%7}, {%8,%9}, {%0,%1,%2,%3};"
        : "+f"(d[0]), "+f"(d[1]), "+f"(d[2]), "+f"(d[3])
        : "r"(a[0]), "r"(a[1]), "r"(a[2]), "r"(a[3]), "r"(b0), "r"(b1));
}
__device__ __forceinline__ uint32_t bf2u(__nv_bfloat16 a, __nv_bfloat16 b) {
    __nv_bfloat162 t; t.x = a; t.y = b;
    return *reinterpret_cast<uint32_t*>(&t);
}

// stage: A_hi 16K | A_lo 16K | B_hi 32K | B_lo 32K = 96KB, double buffered
static constexpr int STG = 98304;
static constexpr int SMEM_BYTES = 2 * STG;   // 192KB

// ============ GEMM: C[128x256] = split-bf16 A @ B^T, bf16x3 ============
// MODE 0: bias+relu -> split bf16 store to g_act1
// MODE 1: bias+relu -> fp32 store to g_act2
template <int MODE>
__global__ void __launch_bounds__(256, 1) gemm_kernel(
    const __nv_bfloat16* __restrict__ Ah, const __nv_bfloat16* __restrict__ Al,
    const __nv_bfloat16* __restrict__ Bh, const __nv_bfloat16* __restrict__ Bl,
    const float* __restrict__ biasA, const float* __restrict__ biasB,
    int K, int ldA, int a_split)
{
    extern __shared__ char smem[];
    const uint32_t sbase = smem_u32(smem);
    const int tid = threadIdx.x, wid = tid >> 5, lid = tid & 31;
    const int n_base = blockIdx.x * 256;
    const int m_base = blockIdx.y * 128;
    const int a_off = (a_split && n_base >= 1024) ? 1024 : 0;
    const float* bias = (n_base >= 1024) ? biasB : biasA;
    const int NS = K >> 6;

    // warp tile 64x64: 2 warps along M, 4 along N
    const int m0 = (wid & 1) * 64, n0 = (wid >> 1) * 64;
    const int lrow = lid & 15;
    const int lcol = (lid >> 4) * 16;   // byte offset 0 / 16

    const int ld_r0 = tid >> 3, ld_c = tid & 7;

    float acc[4][8][4];
#pragma unroll
    for (int mt = 0; mt < 4; ++mt)
#pragma unroll
        for (int j = 0; j < 8; ++j)
#pragma unroll
            for (int q = 0; q < 4; ++q) acc[mt][j][q] = 0.f;

    auto load_stage = [&](int s) {
        if (s < NS) {
            const size_t kb = (size_t)s * 64;
            const uint32_t so = sbase + (uint32_t)(s & 1) * STG;
#pragma unroll
            for (int i = 0; i < 4; ++i) {          // A: 128 rows, hi+lo
                const int row = ld_r0 + i * 32;
                const uint32_t sw = swz((uint32_t)(row * 128 + ld_c * 16));
                const size_t ga = (size_t)(m_base + row) * ldA + a_off + kb + ld_c * 8;
                cp16(so + sw,         Ah + ga);
                cp16(so + 16384 + sw, Al + ga);
            }
#pragma unroll
            for (int i = 0; i < 8; ++i) {          // B: 256 rows, hi+lo
                const int row = ld_r0 + i * 32;
                const uint32_t sw = swz((uint32_t)(row * 128 + ld_c * 16));
                const size_t gb = (size_t)(n_base + row) * K + kb + ld_c * 8;
                cp16(so + 32768 + sw, Bh + gb);
                cp16(so + 65536 + sw, Bl + gb);
            }
        }
        CP_COMMIT();
    };

    load_stage(0);

#pragma unroll 1
    for (int s = 0; s < NS; ++s) {
        load_stage(s + 1);
        CP_WAIT1();
        __syncthreads();
        const uint32_t so = sbase + (uint32_t)(s & 1) * STG;
#pragma unroll
        for (int kk = 0; kk < 4; ++kk) {
            const int kb2 = kk * 32;
            uint32_t af[4][2][4];
#pragma unroll
            for (int mt = 0; mt < 4; ++mt) {
                const uint32_t off = swz((uint32_t)((m0 + mt * 16 + lrow) * 128 + kb2 + lcol));
                ldsm4(af[mt][0], so + off);
                ldsm4(af[mt][1], so + 16384 + off);
            }
#pragma unroll
            for (int j2 = 0; j2 < 4; ++j2) {
                uint32_t bh[4], bl[4];
                const uint32_t off = swz((uint32_t)((n0 + j2 * 16 + lrow) * 128 + kb2 + lcol));
                ldsm4(bh, so + 32768 + off);
                ldsm4(bl, so + 65536 + off);
#pragma unroll
                for (int mt = 0; mt < 4; ++mt)
#pragma unroll
                    for (int h = 0; h < 2; ++h) {
                        float* d = acc[mt][j2 * 2 + h];
                        mma16816(d, af[mt][0], bh[h], bh[2 + h]);
                        mma16816(d, af[mt][0], bl[h], bl[2 + h]);
                        mma16816(d, af[mt][1], bh[h], bh[2 + h]);
                    }
            }
        }
        __syncthreads();
    }

    // epilogue
    const int grp = lid >> 2, qd = lid & 3;
#pragma unroll
    for (int mt = 0; mt < 4; ++mt)
#pragma unroll
        for (int j = 0; j < 8; ++j)
#pragma unroll
            for (int h = 0; h < 2; ++h) {
                const int row = m_base + m0 + mt * 16 + grp + h * 8;
                const int colg = n_base + n0 + (j >> 1) * 16 + (j & 1) * 8 + qd * 2;
                const int cb = colg & 1023;
                const float b0 = __ldg(bias + cb), b1 = __ldg(bias + cb + 1);
                float v0 = fmaxf(acc[mt][j][2 * h]     + b0, 0.f);
                float v1 = fmaxf(acc[mt][j][2 * h + 1] + b1, 0.f);
                const size_t o = (size_t)row * 2048 + colg;
                if (MODE == 0) {
                    __nv_bfloat16 h0 = __float2bfloat16_rn(v0), h1 = __float2bfloat16_rn(v1);
                    *reinterpret_cast<uint32_t*>(g_act1_hi + o) = bf2u(h0, h1);
                    *reinterpret_cast<uint32_t*>(g_act1_lo + o) =
                        bf2u(__float2bfloat16_rn(v0 - __bfloat162float(h0)),
                             __float2bfloat16_rn(v1 - __bfloat162float(h1)));
                } else {
                    float2 f; f.x = v0; f.y = v1;
                    *reinterpret_cast<float2*>(g_act2 + o) = f;
                }
            }
}

// ============ fp32 -> bf16 hi/lo split conversion ============
__global__ void __launch_bounds__(256) conv_split(
    const float* __restrict__ s, __nv_bfloat16* __restrict__ hi,
    __nv_bfloat16* __restrict__ lo, size_t n4)
{
    const size_t i = (size_t)blockIdx.x * 256 + threadIdx.x;
    if (i >= n4) return;
    float4 v = reinterpret_cast<const float4*>(s)[i];
    __nv_bfloat16 h0 = __float2bfloat16_rn(v.x), h1 = __float2bfloat16_rn(v.y);
    __nv_bfloat16 h2 = __float2bfloat16_rn(v.z), h3 = __float2bfloat16_rn(v.w);
    uint2 hp; hp.x = bf2u(h0, h1); hp.y = bf2u(h2, h3);
    reinterpret_cast<uint2*>(hi)[i] = hp;
    uint2 lp;
    lp.x = bf2u(__float2bfloat16_rn(v.x - __bfloat162float(h0)),
                __float2bfloat16_rn(v.y - __bfloat162float(h1)));
    lp.y = bf2u(__float2bfloat16_rn(v.z - __bfloat162float(h2)),
                __float2bfloat16_rn(v.w - __bfloat162float(h3)));
    reinterpret_cast<uint2*>(lo)[i] = lp;
}

// ============ Heads: 53 dot-products of length 1024 per row ============
__global__ void __launch_bounds__(512) heads_kernel(
    const float* __restrict__ w_cls, const float* __restrict__ b_cls,
    const float* __restrict__ w_delta, const float* __restrict__ b_delta,
    const float* __restrict__ w_pos, const float* __restrict__ b_pos,
    const float* __restrict__ w_emb, const float* __restrict__ b_emb)
{
    const int wid = threadIdx.x >> 5, lid = threadIdx.x & 31;
    const int row = blockIdx.x * 16 + wid;
#pragma unroll 1
    for (int o = 0; o < 53; ++o) {
        const float* Wp; const float* bp; int wr, ac;
        if (o < 3)       { Wp = w_cls;   bp = b_cls;   wr = o;      ac = 0; }
        else if (o < 15) { Wp = w_delta; bp = b_delta; wr = o - 3;  ac = 0; }
        else if (o < 21) { Wp = w_pos;   bp = b_pos;   wr = o - 15; ac = 0; }
        else             { Wp = w_emb;   bp = b_emb;   wr = o - 21; ac = 1024; }
        const float* a = g_act2 + (size_t)row * 2048 + ac;
        const float* w = Wp + (size_t)wr * 1024;
        float s = 0.f;
#pragma unroll 8
        for (int k = lid; k < 1024; k += 32) s += a[k] * w[k];
#pragma unroll
        for (int d = 16; d; d >>= 1) s += __shfl_xor_sync(0xFFFFFFFFu, s, d);
        if (lid == 0) g_heads[(size_t)row * 64 + o] = s + bp[wr];
    }
}

// ============ Postprocess: softmax + bbox restore + emb repeat ============
__global__ void __launch_bounds__(128) post_kernel(
    const float* __restrict__ rois, float* __restrict__ out, int out_size)
{
    const int n = blockIdx.x * blockDim.x + threadIdx.x;
    if (n >= 8192) return;
    const float* h = g_heads + (size_t)n * 64;
    float c0 = h[0], c1 = h[1], c2 = h[2];
    float m = fmaxf(c0, fmaxf(c1, c2));
    float e0 = expf(c0 - m), e1 = expf(c1 - m), e2 = expf(c2 - m);
    float inv = 1.f / (e0 + e1 + e2);
    float sc0 = e1 * inv, sc1 = e2 * inv;
    float x1 = rois[n * 5 + 1], y1 = rois[n * 5 + 2];
    float x2 = rois[n * 5 + 3], y2 = rois[n * 5 + 4];
    float bw = x2 - x1, bh = y2 - y1;
    float cx = x1 + 0.5f * bw, cy = y1 + 0.5f * bh;
#pragma unroll
    for (int j = 0; j < 2; ++j) {
        float d0 = h[7 + 4 * j] * 0.1f, d1 = h[8 + 4 * j] * 0.1f;
        float d2 = h[9 + 4 * j] * 0.2f, d3 = h[10 + 4 * j] * 0.2f;
        float p0 = h[17 + 2 * j] * 0.1f, p1 = h[18 + 2 * j] * 0.1f;
        float pcx = d0 * bw + cx, pcy = d1 * bh + cy;
        float pw = expf(d2) * bw, phh = expf(d3) * bh;
        float px = p0 * bw + cx, py = p1 * bh + cy;
        float* ob = out + (size_t)(2 * n + j) * 8;
        ob[0] = pcx - 0.5f * pw;  ob[1] = pcy - 0.5f * phh;
        ob[2] = pcx + 0.5f * pw;  ob[3] = pcy + 0.5f * phh;
        ob[4] = px; ob[5] = py;
        ob[6] = j ? sc1 : sc0;
        ob[7] = (float)(j + 1);
        float* oe = out + 131072 + (size_t)(2 * n + j) * 32;
#pragma unroll
        for (int t = 0; t < 32; ++t) oe[t] = h[21 + t];
    }
    if (n == 0 && out_size > 655360) out[655360] = 2.0f;
}

// ============ launch ============
extern "C" void kernel_launch(void* const* d_in, const int* in_sizes, int n_in,
                              void* d_out, int out_size) {
    const float* pool   = (const float*)d_in[0];
    const float* rois   = (const float*)d_in[1];
    const float* w_fc1  = (const float*)d_in[2];
    const float* b_fc1  = (const float*)d_in[3];
    const float* w_fc2  = (const float*)d_in[4];
    const float* b_fc2  = (const float*)d_in[5];
    const float* w_fc3  = (const float*)d_in[6];
    const float* b_fc3  = (const float*)d_in[7];
    const float* w_fc4  = (const float*)d_in[8];
    const float* b_fc4  = (const float*)d_in[9];
    const float* w_cls  = (const float*)d_in[10];
    const float* b_cls  = (const float*)d_in[11];
    const float* w_delta= (const float*)d_in[12];
    const float* b_delta= (const float*)d_in[13];
    const float* w_pos  = (const float*)d_in[14];
    const float* b_pos  = (const float*)d_in[15];
    const float* w_emb  = (const float*)d_in[16];
    const float* b_emb  = (const float*)d_in[17];
    float* out = (float*)d_out;

    __nv_bfloat16 *Ah, *Al, *W13h, *W13l, *W24h, *W24l, *A1h, *A1l;
    cudaGetSymbolAddress((void**)&Ah,   g_A_hi);
    cudaGetSymbolAddress((void**)&Al,   g_A_lo);
    cudaGetSymbolAddress((void**)&W13h, g_w13_hi);
    cudaGetSymbolAddress((void**)&W13l, g_w13_lo);
    cudaGetSymbolAddress((void**)&W24h, g_w24_hi);
    cudaGetSymbolAddress((void**)&W24l, g_w24_lo);
    cudaGetSymbolAddress((void**)&A1h,  g_act1_hi);
    cudaGetSymbolAddress((void**)&A1l,  g_act1_lo);

    cudaFuncSetAttribute(gemm_kernel<0>, cudaFuncAttributeMaxDynamicSharedMemorySize, SMEM_BYTES);
    cudaFuncSetAttribute(gemm_kernel<1>, cudaFuncAttributeMaxDynamicSharedMemorySize, SMEM_BYTES);

    // 5 conv launches, then gemm1 is launch #6 (ncu -s 5 -c 1 captures it)
    conv_split<<<100352, 256>>>(pool,  Ah,              Al,              25690112);
    conv_split<<<12544,  256>>>(w_fc1, W13h,            W13l,            3211264);
    conv_split<<<12544,  256>>>(w_fc3, W13h + 12845056, W13l + 12845056, 3211264);
    conv_split<<<1024,   256>>>(w_fc2, W24h,            W24l,            262144);
    conv_split<<<1024,   256>>>(w_fc4, W24h + 1048576,  W24l + 1048576,  262144);

    gemm_kernel<0><<<dim3(8, 64), 256, SMEM_BYTES>>>(Ah, Al, W13h, W13l,
                                                     b_fc1, b_fc3, 12544, 12544, 0);
    gemm_kernel<1><<<dim3(8, 64), 256, SMEM_BYTES>>>(A1h, A1l, W24h, W24l,
                                                     b_fc2, b_fc4, 1024, 2048, 1);
    heads_kernel<<<512, 512>>>(w_cls, b_cls, w_delta, b_delta, w_pos, b_pos, w_emb, b_emb);
    post_kernel<<<64, 128>>>(rois, out, out_size);
}